// round 3
// baseline (speedup 1.0000x reference)
#include <cuda_runtime.h>
#include <math.h>

// ---------------- problem constants ----------------
#define B_    8
#define T_    256
#define D_    512
#define W_    32
#define L_    4
#define A_    6
#define H_    8
#define DH    64
#define NSEQ  (B_*T_)        // 2048 sequences
#define MROWS (NSEQ*W_)      // 65536 rows
#define D3    (3*D_)         // 1536
#define DF    (4*D_)         // 2048

// ---------------- scratch (device globals; no allocations) ----------------
__device__ float g_X  [(size_t)MROWS * D_];   // 128 MB : activations
__device__ float g_QKV[(size_t)MROWS * D3];   // 402 MB : qkv / pre-LN temp
__device__ float g_H  [(size_t)MROWS * DF];   // 512 MB : ctx (first M*512) / ff hidden

// ---------------- build X = feats[window] + pos_embed ----------------
__global__ __launch_bounds__(256)
void buildx_k(const float* __restrict__ feats, const float* __restrict__ pos)
{
    int idx = blockIdx.x * 256 + threadIdx.x;        // float4 index; total 8388608
    int d4  = idx & 127;                             // D/4 = 128
    int w   = (idx >> 7) & 31;
    int seq = idx >> 12;
    int t   = seq & (T_ - 1);
    int f   = t + 1 - W_ + w; if (f < 0) f = 0;
    int frame = (seq - t) + f;                       // b*T + f
    float4 a  = *(const float4*)(feats + (size_t)frame * D_ + d4 * 4);
    float4 p4 = *(const float4*)(pos   + (size_t)w     * D_ + d4 * 4);
    float4 o  = make_float4(a.x + p4.x, a.y + p4.y, a.z + p4.z, a.w + p4.w);
    *(float4*)(g_X + (size_t)idx * 4) = o;
}

// ---------------- generic fp32 GEMM: C = A(MxK) * Bw(NxK)^T + bias (+resid)(relu) ----------------
template<int RELU>
__global__ __launch_bounds__(256)
void gemm_k(const float* __restrict__ A, const float* __restrict__ Bw,
            const float* __restrict__ bias, const float* __restrict__ resid,
            float* __restrict__ C, int M, int N, int K)
{
    __shared__ float As[16][128];
    __shared__ float Bs[16][128];
    const int tid = threadIdx.x;
    const int n0  = blockIdx.x * 128;
    const int m0  = blockIdx.y * 128;
    const int tn  = tid & 15;
    const int tm  = tid >> 4;

    float acc[8][8];
#pragma unroll
    for (int i = 0; i < 8; i++)
#pragma unroll
        for (int j = 0; j < 8; j++) acc[i][j] = 0.f;

    for (int kt = 0; kt < K; kt += 16) {
#pragma unroll
        for (int l = 0; l < 2; l++) {
            int li = tid * 2 + l;                    // 0..511
            int r  = li >> 2;
            int kq = (li & 3) * 4;
            float4 v = *(const float4*)(A  + (size_t)(m0 + r) * K + kt + kq);
            As[kq + 0][r] = v.x; As[kq + 1][r] = v.y;
            As[kq + 2][r] = v.z; As[kq + 3][r] = v.w;
            float4 u = *(const float4*)(Bw + (size_t)(n0 + r) * K + kt + kq);
            Bs[kq + 0][r] = u.x; Bs[kq + 1][r] = u.y;
            Bs[kq + 2][r] = u.z; Bs[kq + 3][r] = u.w;
        }
        __syncthreads();
#pragma unroll
        for (int k = 0; k < 16; k++) {
            float a[8], b[8];
#pragma unroll
            for (int i = 0; i < 8; i++) a[i] = As[k][tm * 8 + i];
#pragma unroll
            for (int j = 0; j < 8; j++) b[j] = Bs[k][tn * 8 + j];
#pragma unroll
            for (int i = 0; i < 8; i++)
#pragma unroll
                for (int j = 0; j < 8; j++) acc[i][j] += a[i] * b[j];
        }
        __syncthreads();
    }

#pragma unroll
    for (int i = 0; i < 8; i++) {
        int m = m0 + tm * 8 + i;
#pragma unroll
        for (int jq = 0; jq < 2; jq++) {
            int n = n0 + tn * 8 + jq * 4;
            float4 bv4 = *(const float4*)(bias + n);
            float4 o;
            o.x = acc[i][jq * 4 + 0] + bv4.x;
            o.y = acc[i][jq * 4 + 1] + bv4.y;
            o.z = acc[i][jq * 4 + 2] + bv4.z;
            o.w = acc[i][jq * 4 + 3] + bv4.w;
            if (resid) {
                float4 r4 = *(const float4*)(resid + (size_t)m * N + n);
                o.x += r4.x; o.y += r4.y; o.z += r4.z; o.w += r4.w;
            }
            if (RELU) {
                o.x = fmaxf(o.x, 0.f); o.y = fmaxf(o.y, 0.f);
                o.z = fmaxf(o.z, 0.f); o.w = fmaxf(o.w, 0.f);
            }
            *(float4*)(C + (size_t)m * N + n) = o;
        }
    }
}

// ---------------- per-(seq,head) causal attention over W=32 ----------------
__global__ __launch_bounds__(128)
void attn_k(const float* __restrict__ qkv, float* __restrict__ ctx)
{
    const int sh  = blockIdx.x;
    const int seq = sh >> 3;
    const int h   = sh & 7;
    __shared__ float q[W_][DH], k[W_][DH], v[W_][DH];
    __shared__ float p[W_][W_ + 1];
    const int tid = threadIdx.x;

    const size_t base = (size_t)seq * W_ * D3 + h * DH;
    for (int l = tid; l < W_ * 16; l += 128) {       // 512 float4 per matrix
        int w  = l >> 4;
        int d4 = (l & 15) * 4;
        const float* src = qkv + base + (size_t)w * D3;
        *(float4*)&q[w][d4] = *(const float4*)(src + d4);
        *(float4*)&k[w][d4] = *(const float4*)(src + 512 + d4);
        *(float4*)&v[w][d4] = *(const float4*)(src + 1024 + d4);
    }
    __syncthreads();

    for (int l = tid; l < W_ * W_; l += 128) {
        int r = l >> 5, c = l & 31;
        if (c <= r) {
            float s = 0.f;
#pragma unroll
            for (int e = 0; e < DH; e++) s += q[r][e] * k[c][e];
            p[r][c] = s * 0.125f;                    // 1/sqrt(64)
        }
    }
    __syncthreads();

    if (tid < W_) {
        int r = tid;
        float mx = -1e30f;
        for (int c = 0; c <= r; c++) mx = fmaxf(mx, p[r][c]);
        float sum = 0.f;
        for (int c = 0; c <= r; c++) { float e = expf(p[r][c] - mx); p[r][c] = e; sum += e; }
        float inv = 1.f / sum;
        for (int c = 0; c <= r; c++) p[r][c] *= inv;
        for (int c = r + 1; c < W_; c++) p[r][c] = 0.f;
    }
    __syncthreads();

    for (int l = tid; l < W_ * DH; l += 128) {
        int r = l >> 6, d = l & 63;
        float s = 0.f;
#pragma unroll
        for (int c = 0; c < W_; c++) s += p[r][c] * v[c][d];
        ctx[((size_t)seq * W_ + r) * D_ + h * DH + d] = s;
    }
}

// ---------------- row LayerNorm over D=512 ----------------
__global__ __launch_bounds__(128)
void ln_k(const float* __restrict__ in, const float* __restrict__ g,
          const float* __restrict__ b, float* __restrict__ out)
{
    const int row = blockIdx.x;
    const int tid = threadIdx.x;
    const float* x = in + (size_t)row * D_;
    float4 v = *(const float4*)(x + tid * 4);
    float s  = v.x + v.y + v.z + v.w;
    float sq = v.x * v.x + v.y * v.y + v.z * v.z + v.w * v.w;
    __shared__ float red[10];
    int wid = tid >> 5, lane = tid & 31;
#pragma unroll
    for (int off = 16; off; off >>= 1) {
        s  += __shfl_down_sync(0xffffffffu, s,  off);
        sq += __shfl_down_sync(0xffffffffu, sq, off);
    }
    if (lane == 0) { red[wid] = s; red[4 + wid] = sq; }
    __syncthreads();
    if (tid == 0) {
        float ts  = red[0] + red[1] + red[2] + red[3];
        float tsq = red[4] + red[5] + red[6] + red[7];
        float mean = ts * (1.f / D_);
        float var  = tsq * (1.f / D_) - mean * mean;
        red[8] = mean;
        red[9] = rsqrtf(var + 1e-5f);
    }
    __syncthreads();
    float mean = red[8], rstd = red[9];
    float4 g4 = *(const float4*)(g + tid * 4);
    float4 b4 = *(const float4*)(b + tid * 4);
    float4 o;
    o.x = (v.x - mean) * rstd * g4.x + b4.x;
    o.y = (v.y - mean) * rstd * g4.y + b4.y;
    o.z = (v.z - mean) * rstd * g4.z + b4.z;
    o.w = (v.w - mean) * rstd * g4.w + b4.w;
    *(float4*)(out + (size_t)row * D_ + tid * 4) = o;
}

// ---------------- head: logits (B,T,A) then values (B,T) ----------------
__global__ __launch_bounds__(256)
void head_k(const float* __restrict__ x, const float* __restrict__ Wp,
            const float* __restrict__ bp, const float* __restrict__ Wv,
            const float* __restrict__ bv, float* __restrict__ out)
{
    const int seq = blockIdx.x;
    __shared__ float tok[D_];
    const int tid = threadIdx.x;
    const float* src = x + ((size_t)seq * W_ + (W_ - 1)) * D_;
    *(float2*)&tok[tid * 2] = *(const float2*)(src + tid * 2);
    __syncthreads();
    int wid = tid >> 5, lane = tid & 31;
    if (wid < 7) {
        const float* wrow = (wid < 6) ? (Wp + wid * D_) : Wv;
        float s = 0.f;
        for (int i = lane; i < D_; i += 32) s += tok[i] * wrow[i];
#pragma unroll
        for (int off = 16; off; off >>= 1) s += __shfl_down_sync(0xffffffffu, s, off);
        if (lane == 0) {
            if (wid < 6) out[(size_t)seq * A_ + wid] = s + bp[wid];
            else         out[(size_t)NSEQ * A_ + seq] = s + bv[0];
        }
    }
}

// ---------------- launch ----------------
extern "C" void kernel_launch(void* const* d_in, const int* in_sizes, int n_in,
                              void* d_out, int out_size)
{
    const float* feats = (const float*)d_in[0];
    const float* pos   = (const float*)d_in[1];
    const float* Wqkv  = (const float*)d_in[2];
    const float* bqkv  = (const float*)d_in[3];
    const float* Wo    = (const float*)d_in[4];
    const float* bo    = (const float*)d_in[5];
    const float* ln1g  = (const float*)d_in[6];
    const float* ln1b  = (const float*)d_in[7];
    const float* W1    = (const float*)d_in[8];
    const float* b1    = (const float*)d_in[9];
    const float* W2    = (const float*)d_in[10];
    const float* b2    = (const float*)d_in[11];
    const float* ln2g  = (const float*)d_in[12];
    const float* ln2b  = (const float*)d_in[13];
    const float* Wp    = (const float*)d_in[14];
    const float* bp    = (const float*)d_in[15];
    const float* Wv    = (const float*)d_in[16];
    const float* bv    = (const float*)d_in[17];
    float* out = (float*)d_out;

    float *X, *QKV, *Hb;
    cudaGetSymbolAddress((void**)&X,   g_X);
    cudaGetSymbolAddress((void**)&QKV, g_QKV);
    cudaGetSymbolAddress((void**)&Hb,  g_H);

    dim3 blk(256);
    buildx_k<<<(MROWS * D_ / 4) / 256, blk>>>(feats, pos);

    for (int i = 0; i < L_; i++) {
        // qkv = X @ Wqkv^T + bqkv
        gemm_k<0><<<dim3(D3 / 128, MROWS / 128), blk>>>(
            X, Wqkv + (size_t)i * D3 * D_, bqkv + i * D3, nullptr, QKV, MROWS, D3, D_);
        // attention -> ctx (into g_H, stride D)
        attn_k<<<NSEQ * H_, 128>>>(QKV, Hb);
        // preLN1 = X + ctx @ Wo^T + bo  (into g_QKV)
        gemm_k<0><<<dim3(D_ / 128, MROWS / 128), blk>>>(
            Hb, Wo + (size_t)i * D_ * D_, bo + i * D_, X, QKV, MROWS, D_, D_);
        ln_k<<<MROWS, 128>>>(QKV, ln1g + i * D_, ln1b + i * D_, X);
        // h = relu(X @ W1^T + b1)
        gemm_k<1><<<dim3(DF / 128, MROWS / 128), blk>>>(
            X, W1 + (size_t)i * DF * D_, b1 + i * DF, nullptr, Hb, MROWS, DF, D_);
        // preLN2 = X + h @ W2^T + b2
        gemm_k<0><<<dim3(D_ / 128, MROWS / 128), blk>>>(
            Hb, W2 + (size_t)i * D_ * DF, b2 + i * D_, X, QKV, MROWS, D_, DF);
        ln_k<<<MROWS, 128>>>(QKV, ln2g + i * D_, ln2b + i * D_, X);
    }

    head_k<<<NSEQ, 256>>>(X, Wp, bp, Wv, bv, out);
}

// round 5
// speedup vs baseline: 2.9151x; 2.9151x over previous
#include <cuda_runtime.h>
#include <math.h>
#include <stdint.h>

// ---------------- problem constants ----------------
#define B_    8
#define T_    256
#define D_    512
#define W_    32
#define L_    4
#define A_    6
#define H_    8
#define DH    64
#define NSEQ  (B_*T_)        // 2048 sequences
#define MROWS (NSEQ*W_)      // 65536 rows
#define D3    (3*D_)         // 1536
#define DF    (4*D_)         // 2048

#define BK    32             // K chunk
#define SSTR  36             // smem row stride in floats (conflict-free fragments)
#define ABUF  (128*SSTR)     // 4608 floats per matrix tile
#define TGEMM_SMEM (2*2*ABUF*4)   // 73728 B: double-buffered A+B

// ---------------- scratch (device globals; no allocations) ----------------
__device__ float g_X  [(size_t)MROWS * D_];
__device__ float g_QKV[(size_t)MROWS * D3];
__device__ float g_H  [(size_t)MROWS * DF];

// ---------------- PTX helpers ----------------
__device__ __forceinline__ uint32_t smem_u32(const void* p) {
    uint32_t a;
    asm("{ .reg .u64 t; cvta.to.shared.u64 t, %1; cvt.u32.u64 %0, t; }" : "=r"(a) : "l"(p));
    return a;
}
__device__ __forceinline__ uint32_t f2tf32(float f) {
    uint32_t r;
    asm("cvt.rna.tf32.f32 %0, %1;" : "=r"(r) : "f"(f));
    return r;
}
__device__ __forceinline__ void cp16(uint32_t s, const void* g) {
    asm volatile("cp.async.cg.shared.global [%0], [%1], 16;" :: "r"(s), "l"(g));
}
__device__ __forceinline__ void cp_commit() {
    asm volatile("cp.async.commit_group;" ::: "memory");
}
__device__ __forceinline__ void cp_wait1() {
    asm volatile("cp.async.wait_group 1;" ::: "memory");
}
__device__ __forceinline__ void cp_wait0() {
    asm volatile("cp.async.wait_group 0;" ::: "memory");
}
__device__ __forceinline__ void mma_tf32(float4& c, const uint32_t a[4], const uint32_t b[2]) {
    asm volatile(
        "mma.sync.aligned.m16n8k8.row.col.f32.tf32.tf32.f32 "
        "{%0,%1,%2,%3}, {%4,%5,%6,%7}, {%8,%9}, {%0,%1,%2,%3};"
        : "+f"(c.x), "+f"(c.y), "+f"(c.z), "+f"(c.w)
        : "r"(a[0]), "r"(a[1]), "r"(a[2]), "r"(a[3]), "r"(b[0]), "r"(b[1]));
}

// ---------------- build X = feats[window] + pos_embed ----------------
__global__ __launch_bounds__(256)
void buildx_k(const float* __restrict__ feats, const float* __restrict__ pos)
{
    int idx = blockIdx.x * 256 + threadIdx.x;
    int d4  = idx & 127;
    int w   = (idx >> 7) & 31;
    int seq = idx >> 12;
    int t   = seq & (T_ - 1);
    int f   = t + 1 - W_ + w; if (f < 0) f = 0;
    int frame = (seq - t) + f;
    float4 a  = *(const float4*)(feats + (size_t)frame * D_ + d4 * 4);
    float4 p4 = *(const float4*)(pos   + (size_t)w     * D_ + d4 * 4);
    float4 o  = make_float4(a.x + p4.x, a.y + p4.y, a.z + p4.z, a.w + p4.w);
    *(float4*)(g_X + (size_t)idx * 4) = o;
}

// ---------------- tf32 mma.sync GEMM: C = A(MxK) * Bw(NxK)^T + bias (+resid)(relu) ----------------
// 128x128 tile, 256 threads (8 warps 2x4, warp tile 64x32), cp.async double buffer.
template<int RELU>
__global__ __launch_bounds__(256)
void tgemm_k(const float* __restrict__ A, const float* __restrict__ Bw,
             const float* __restrict__ bias, const float* __restrict__ resid,
             float* __restrict__ C, int M, int N, int K)
{
    extern __shared__ float sm[];
    const uint32_t sm0 = smem_u32(sm);

    const int tid  = threadIdx.x;
    const int lane = tid & 31;
    const int wid  = tid >> 5;
    const int wm   = wid >> 2;          // 0..1
    const int wn   = wid & 3;           // 0..3
    const int l4   = lane >> 2;         // 0..7
    const int lm   = lane & 3;          // 0..3
    const int n0   = blockIdx.x * 128;
    const int m0   = blockIdx.y * 128;

    // staging indices: each thread copies 4x16B for A and 4x16B for B per chunk
    const int srow = tid >> 3;          // base row (stride 32 rows per step)
    const int sq   = (tid & 7) * 4;     // float offset in the 32-wide chunk row

    const float* Abase = A  + (size_t)(m0 + srow) * K + sq;
    const float* Bbase = Bw + (size_t)(n0 + srow) * K + sq;
    const uint32_t sAoff = (uint32_t)(srow * SSTR + sq) * 4;

    auto stage = [&](int c, int pb) {
        uint32_t sA = sm0 + (uint32_t)(pb * 2 * ABUF) * 4 + sAoff;
        uint32_t sB = sA + (uint32_t)ABUF * 4;
        const float* ga = Abase + (size_t)c * BK;
        const float* gb = Bbase + (size_t)c * BK;
#pragma unroll
        for (int i = 0; i < 4; i++) {
            cp16(sA + i * 32 * SSTR * 4, ga + (size_t)(i * 32) * K);
            cp16(sB + i * 32 * SSTR * 4, gb + (size_t)(i * 32) * K);
        }
        cp_commit();
    };

    float4 acc[4][4];
#pragma unroll
    for (int i = 0; i < 4; i++)
#pragma unroll
        for (int j = 0; j < 4; j++) acc[i][j] = make_float4(0.f, 0.f, 0.f, 0.f);

    const int nchunk = K / BK;
    stage(0, 0);

    for (int c = 0; c < nchunk; c++) {
        const int pb = c & 1;
        if (c + 1 < nchunk) { stage(c + 1, pb ^ 1); cp_wait1(); }
        else                { cp_wait0(); }
        __syncthreads();

        const float* sA = sm + pb * 2 * ABUF;
        const float* sB = sA + ABUF;
        const float* aB = sA + (wm * 64 + l4) * SSTR + lm;   // A frag base
        const float* bB = sB + (wn * 32 + l4) * SSTR + lm;   // B frag base

#pragma unroll
        for (int ks = 0; ks < 4; ks++) {
            const int kk = ks * 8;
            uint32_t af[4][4], bf[4][2];
#pragma unroll
            for (int mt = 0; mt < 4; mt++) {
                const float* p = aB + mt * 16 * SSTR + kk;
                af[mt][0] = f2tf32(p[0]);
                af[mt][1] = f2tf32(p[8 * SSTR]);
                af[mt][2] = f2tf32(p[4]);
                af[mt][3] = f2tf32(p[8 * SSTR + 4]);
            }
#pragma unroll
            for (int nt = 0; nt < 4; nt++) {
                const float* p = bB + nt * 8 * SSTR + kk;
                bf[nt][0] = f2tf32(p[0]);
                bf[nt][1] = f2tf32(p[4]);
            }
#pragma unroll
            for (int mt = 0; mt < 4; mt++)
#pragma unroll
                for (int nt = 0; nt < 4; nt++)
                    mma_tf32(acc[mt][nt], af[mt], bf[nt]);
        }
        __syncthreads();
    }

    // epilogue: bias (+resid)(relu), write float2 pairs
#pragma unroll
    for (int mt = 0; mt < 4; mt++) {
        const int m = m0 + wm * 64 + mt * 16 + l4;
#pragma unroll
        for (int nt = 0; nt < 4; nt++) {
            const int n = n0 + wn * 32 + nt * 8 + lm * 2;
            float4 cc = acc[mt][nt];
            float2 bv = *(const float2*)(bias + n);
            cc.x += bv.x; cc.y += bv.y;
            cc.z += bv.x; cc.w += bv.y;
            if (resid) {
                float2 r0 = *(const float2*)(resid + (size_t)m * N + n);
                float2 r1 = *(const float2*)(resid + (size_t)(m + 8) * N + n);
                cc.x += r0.x; cc.y += r0.y;
                cc.z += r1.x; cc.w += r1.y;
            }
            if (RELU) {
                cc.x = fmaxf(cc.x, 0.f); cc.y = fmaxf(cc.y, 0.f);
                cc.z = fmaxf(cc.z, 0.f); cc.w = fmaxf(cc.w, 0.f);
            }
            *(float2*)(C + (size_t)m * N + n)       = make_float2(cc.x, cc.y);
            *(float2*)(C + (size_t)(m + 8) * N + n) = make_float2(cc.z, cc.w);
        }
    }
}

// ---------------- per-(seq,head) causal attention over W=32 ----------------
__global__ __launch_bounds__(128)
void attn_k(const float* __restrict__ qkv, float* __restrict__ ctx)
{
    const int sh  = blockIdx.x;
    const int seq = sh >> 3;
    const int h   = sh & 7;
    __shared__ float q[W_][DH], k[W_][DH], v[W_][DH];
    __shared__ float p[W_][W_ + 1];
    const int tid = threadIdx.x;

    const size_t base = (size_t)seq * W_ * D3 + h * DH;
    for (int l = tid; l < W_ * 16; l += 128) {
        int w  = l >> 4;
        int d4 = (l & 15) * 4;
        const float* src = qkv + base + (size_t)w * D3;
        *(float4*)&q[w][d4] = *(const float4*)(src + d4);
        *(float4*)&k[w][d4] = *(const float4*)(src + 512 + d4);
        *(float4*)&v[w][d4] = *(const float4*)(src + 1024 + d4);
    }
    __syncthreads();

    for (int l = tid; l < W_ * W_; l += 128) {
        int r = l >> 5, c = l & 31;
        if (c <= r) {
            float s = 0.f;
#pragma unroll
            for (int e = 0; e < DH; e++) s += q[r][e] * k[c][e];
            p[r][c] = s * 0.125f;
        }
    }
    __syncthreads();

    if (tid < W_) {
        int r = tid;
        float mx = -1e30f;
        for (int c = 0; c <= r; c++) mx = fmaxf(mx, p[r][c]);
        float sum = 0.f;
        for (int c = 0; c <= r; c++) { float e = expf(p[r][c] - mx); p[r][c] = e; sum += e; }
        float inv = 1.f / sum;
        for (int c = 0; c <= r; c++) p[r][c] *= inv;
        for (int c = r + 1; c < W_; c++) p[r][c] = 0.f;
    }
    __syncthreads();

    for (int l = tid; l < W_ * DH; l += 128) {
        int r = l >> 6, d = l & 63;
        float s = 0.f;
#pragma unroll
        for (int c = 0; c < W_; c++) s += p[r][c] * v[c][d];
        ctx[((size_t)seq * W_ + r) * D_ + h * DH + d] = s;
    }
}

// ---------------- row LayerNorm over D=512 ----------------
__global__ __launch_bounds__(128)
void ln_k(const float* __restrict__ in, const float* __restrict__ g,
          const float* __restrict__ b, float* __restrict__ out)
{
    const int row = blockIdx.x;
    const int tid = threadIdx.x;
    const float* x = in + (size_t)row * D_;
    float4 v = *(const float4*)(x + tid * 4);
    float s  = v.x + v.y + v.z + v.w;
    float sq = v.x * v.x + v.y * v.y + v.z * v.z + v.w * v.w;
    __shared__ float red[10];
    int wid = tid >> 5, lane = tid & 31;
#pragma unroll
    for (int off = 16; off; off >>= 1) {
        s  += __shfl_down_sync(0xffffffffu, s,  off);
        sq += __shfl_down_sync(0xffffffffu, sq, off);
    }
    if (lane == 0) { red[wid] = s; red[4 + wid] = sq; }
    __syncthreads();
    if (tid == 0) {
        float ts  = red[0] + red[1] + red[2] + red[3];
        float tsq = red[4] + red[5] + red[6] + red[7];
        float mean = ts * (1.f / D_);
        float var  = tsq * (1.f / D_) - mean * mean;
        red[8] = mean;
        red[9] = rsqrtf(var + 1e-5f);
    }
    __syncthreads();
    float mean = red[8], rstd = red[9];
    float4 g4 = *(const float4*)(g + tid * 4);
    float4 b4 = *(const float4*)(b + tid * 4);
    float4 o;
    o.x = (v.x - mean) * rstd * g4.x + b4.x;
    o.y = (v.y - mean) * rstd * g4.y + b4.y;
    o.z = (v.z - mean) * rstd * g4.z + b4.z;
    o.w = (v.w - mean) * rstd * g4.w + b4.w;
    *(float4*)(out + (size_t)row * D_ + tid * 4) = o;
}

// ---------------- head: logits (B,T,A) then values (B,T) ----------------
__global__ __launch_bounds__(256)
void head_k(const float* __restrict__ x, const float* __restrict__ Wp,
            const float* __restrict__ bp, const float* __restrict__ Wv,
            const float* __restrict__ bv, float* __restrict__ out)
{
    const int seq = blockIdx.x;
    __shared__ float tok[D_];
    const int tid = threadIdx.x;
    const float* src = x + ((size_t)seq * W_ + (W_ - 1)) * D_;
    *(float2*)&tok[tid * 2] = *(const float2*)(src + tid * 2);
    __syncthreads();
    int wid = tid >> 5, lane = tid & 31;
    if (wid < 7) {
        const float* wrow = (wid < 6) ? (Wp + wid * D_) : Wv;
        float s = 0.f;
        for (int i = lane; i < D_; i += 32) s += tok[i] * wrow[i];
#pragma unroll
        for (int off = 16; off; off >>= 1) s += __shfl_down_sync(0xffffffffu, s, off);
        if (lane == 0) {
            if (wid < 6) out[(size_t)seq * A_ + wid] = s + bp[wid];
            else         out[(size_t)NSEQ * A_ + seq] = s + bv[0];
        }
    }
}

// ---------------- launch ----------------
extern "C" void kernel_launch(void* const* d_in, const int* in_sizes, int n_in,
                              void* d_out, int out_size)
{
    const float* feats = (const float*)d_in[0];
    const float* pos   = (const float*)d_in[1];
    const float* Wqkv  = (const float*)d_in[2];
    const float* bqkv  = (const float*)d_in[3];
    const float* Wo    = (const float*)d_in[4];
    const float* bo    = (const float*)d_in[5];
    const float* ln1g  = (const float*)d_in[6];
    const float* ln1b  = (const float*)d_in[7];
    const float* W1    = (const float*)d_in[8];
    const float* b1    = (const float*)d_in[9];
    const float* W2    = (const float*)d_in[10];
    const float* b2    = (const float*)d_in[11];
    const float* ln2g  = (const float*)d_in[12];
    const float* ln2b  = (const float*)d_in[13];
    const float* Wp    = (const float*)d_in[14];
    const float* bp    = (const float*)d_in[15];
    const float* Wv    = (const float*)d_in[16];
    const float* bv    = (const float*)d_in[17];
    float* out = (float*)d_out;

    float *X, *QKV, *Hb;
    cudaGetSymbolAddress((void**)&X,   g_X);
    cudaGetSymbolAddress((void**)&QKV, g_QKV);
    cudaGetSymbolAddress((void**)&Hb,  g_H);

    static int attr_done = 0;
    if (!attr_done) {
        cudaFuncSetAttribute(tgemm_k<0>, cudaFuncAttributeMaxDynamicSharedMemorySize, TGEMM_SMEM);
        cudaFuncSetAttribute(tgemm_k<1>, cudaFuncAttributeMaxDynamicSharedMemorySize, TGEMM_SMEM);
        attr_done = 1;
    }

    buildx_k<<<(MROWS * D_ / 4) / 256, 256>>>(feats, pos);

    for (int i = 0; i < L_; i++) {
        // qkv = X @ Wqkv^T + bqkv
        tgemm_k<0><<<dim3(D3 / 128, MROWS / 128), 256, TGEMM_SMEM>>>(
            X, Wqkv + (size_t)i * D3 * D_, bqkv + i * D3, nullptr, QKV, MROWS, D3, D_);
        // attention -> ctx
        attn_k<<<NSEQ * H_, 128>>>(QKV, Hb);
        // preLN1 = X + ctx @ Wo^T + bo
        tgemm_k<0><<<dim3(D_ / 128, MROWS / 128), 256, TGEMM_SMEM>>>(
            Hb, Wo + (size_t)i * D_ * D_, bo + i * D_, X, QKV, MROWS, D_, D_);
        ln_k<<<MROWS, 128>>>(QKV, ln1g + i * D_, ln1b + i * D_, X);
        // h = relu(X @ W1^T + b1)
        tgemm_k<1><<<dim3(DF / 128, MROWS / 128), 256, TGEMM_SMEM>>>(
            X, W1 + (size_t)i * DF * D_, b1 + i * DF, nullptr, Hb, MROWS, DF, D_);
        // preLN2 = X + h @ W2^T + b2
        tgemm_k<0><<<dim3(D_ / 128, MROWS / 128), 256, TGEMM_SMEM>>>(
            Hb, W2 + (size_t)i * D_ * DF, b2 + i * D_, X, QKV, MROWS, D_, DF);
        ln_k<<<MROWS, 128>>>(QKV, ln2g + i * D_, ln2b + i * D_, X);
    }

    head_k<<<NSEQ, 256>>>(X, Wp, bp, Wv, bv, out);
}

// round 6
// speedup vs baseline: 3.2866x; 1.1274x over previous
#include <cuda_runtime.h>
#include <math.h>
#include <stdint.h>

// ---------------- problem constants ----------------
#define B_    8
#define T_    256
#define D_    512
#define W_    32
#define L_    4
#define A_    6
#define H_    8
#define DH    64
#define NSEQ  (B_*T_)        // 2048 sequences
#define MROWS (NSEQ*W_)      // 65536 rows
#define D3    (3*D_)         // 1536
#define DF    (4*D_)         // 2048

#define BK    32             // K chunk
#define SSTR  36             // smem row stride in floats (conflict-free fragments)
#define ABUF  (128*SSTR)     // 4608 floats per matrix tile
#define TGEMM_SMEM (2*2*ABUF*4)   // 73728 B: double-buffered A+B

// ---------------- scratch (device globals; no allocations) ----------------
__device__ float g_X  [(size_t)MROWS * D_];
__device__ float g_QKV[(size_t)MROWS * D3];
__device__ float g_H  [(size_t)MROWS * DF];

// ---------------- PTX helpers ----------------
__device__ __forceinline__ uint32_t smem_u32(const void* p) {
    uint32_t a;
    asm("{ .reg .u64 t; cvta.to.shared.u64 t, %1; cvt.u32.u64 %0, t; }" : "=r"(a) : "l"(p));
    return a;
}
__device__ __forceinline__ uint32_t f2tf32(float f) {
    uint32_t r;
    asm("cvt.rna.tf32.f32 %0, %1;" : "=r"(r) : "f"(f));
    return r;
}
__device__ __forceinline__ void cp16(uint32_t s, const void* g) {
    asm volatile("cp.async.cg.shared.global [%0], [%1], 16;" :: "r"(s), "l"(g));
}
__device__ __forceinline__ void cp_commit() {
    asm volatile("cp.async.commit_group;" ::: "memory");
}
__device__ __forceinline__ void cp_wait1() {
    asm volatile("cp.async.wait_group 1;" ::: "memory");
}
__device__ __forceinline__ void cp_wait0() {
    asm volatile("cp.async.wait_group 0;" ::: "memory");
}
__device__ __forceinline__ void mma_tf32(float4& c, const uint32_t a[4], const uint32_t b[2]) {
    asm volatile(
        "mma.sync.aligned.m16n8k8.row.col.f32.tf32.tf32.f32 "
        "{%0,%1,%2,%3}, {%4,%5,%6,%7}, {%8,%9}, {%0,%1,%2,%3};"
        : "+f"(c.x), "+f"(c.y), "+f"(c.z), "+f"(c.w)
        : "r"(a[0]), "r"(a[1]), "r"(a[2]), "r"(a[3]), "r"(b[0]), "r"(b[1]));
}

// ---------------- build X = feats[window] + pos_embed ----------------
__global__ __launch_bounds__(256)
void buildx_k(const float* __restrict__ feats, const float* __restrict__ pos)
{
    int idx = blockIdx.x * 256 + threadIdx.x;
    int d4  = idx & 127;
    int w   = (idx >> 7) & 31;
    int seq = idx >> 12;
    int t   = seq & (T_ - 1);
    int f   = t + 1 - W_ + w; if (f < 0) f = 0;
    int frame = (seq - t) + f;
    float4 a  = *(const float4*)(feats + (size_t)frame * D_ + d4 * 4);
    float4 p4 = *(const float4*)(pos   + (size_t)w     * D_ + d4 * 4);
    float4 o  = make_float4(a.x + p4.x, a.y + p4.y, a.z + p4.z, a.w + p4.w);
    *(float4*)(g_X + (size_t)idx * 4) = o;
}

// ---------------- tf32 mma.sync GEMM: C = A(MxK) * Bw(NxK)^T + bias (+resid)(relu) ----------------
// 128x128 tile, 256 threads (8 warps 2x4, warp tile 64x32), cp.async double buffer.
template<int RELU>
__global__ __launch_bounds__(256)
void tgemm_k(const float* __restrict__ A, const float* __restrict__ Bw,
             const float* __restrict__ bias, const float* __restrict__ resid,
             float* __restrict__ C, int M, int N, int K)
{
    extern __shared__ float sm[];
    const uint32_t sm0 = smem_u32(sm);

    const int tid  = threadIdx.x;
    const int lane = tid & 31;
    const int wid  = tid >> 5;
    const int wm   = wid >> 2;          // 0..1
    const int wn   = wid & 3;           // 0..3
    const int l4   = lane >> 2;         // 0..7
    const int lm   = lane & 3;          // 0..3
    const int n0   = blockIdx.x * 128;
    const int m0   = blockIdx.y * 128;

    const int srow = tid >> 3;          // base row
    const int sq   = (tid & 7) * 4;

    const float* Abase = A  + (size_t)(m0 + srow) * K + sq;
    const float* Bbase = Bw + (size_t)(n0 + srow) * K + sq;
    const uint32_t sAoff = (uint32_t)(srow * SSTR + sq) * 4;

    auto stage = [&](int c, int pb) {
        uint32_t sA = sm0 + (uint32_t)(pb * 2 * ABUF) * 4 + sAoff;
        uint32_t sB = sA + (uint32_t)ABUF * 4;
        const float* ga = Abase + (size_t)c * BK;
        const float* gb = Bbase + (size_t)c * BK;
#pragma unroll
        for (int i = 0; i < 4; i++) {
            cp16(sA + i * 32 * SSTR * 4, ga + (size_t)(i * 32) * K);
            cp16(sB + i * 32 * SSTR * 4, gb + (size_t)(i * 32) * K);
        }
        cp_commit();
    };

    float4 acc[4][4];
#pragma unroll
    for (int i = 0; i < 4; i++)
#pragma unroll
        for (int j = 0; j < 4; j++) acc[i][j] = make_float4(0.f, 0.f, 0.f, 0.f);

    const int nchunk = K / BK;
    stage(0, 0);

    for (int c = 0; c < nchunk; c++) {
        const int pb = c & 1;
        if (c + 1 < nchunk) { stage(c + 1, pb ^ 1); cp_wait1(); }
        else                { cp_wait0(); }
        __syncthreads();

        const float* sA = sm + pb * 2 * ABUF;
        const float* sB = sA + ABUF;
        const float* aB = sA + (wm * 64 + l4) * SSTR + lm;
        const float* bB = sB + (wn * 32 + l4) * SSTR + lm;

#pragma unroll
        for (int ks = 0; ks < 4; ks++) {
            const int kk = ks * 8;
            uint32_t af[4][4], bf[4][2];
#pragma unroll
            for (int mt = 0; mt < 4; mt++) {
                const float* p = aB + mt * 16 * SSTR + kk;
                af[mt][0] = f2tf32(p[0]);
                af[mt][1] = f2tf32(p[8 * SSTR]);
                af[mt][2] = f2tf32(p[4]);
                af[mt][3] = f2tf32(p[8 * SSTR + 4]);
            }
#pragma unroll
            for (int nt = 0; nt < 4; nt++) {
                const float* p = bB + nt * 8 * SSTR + kk;
                bf[nt][0] = f2tf32(p[0]);
                bf[nt][1] = f2tf32(p[4]);
            }
#pragma unroll
            for (int mt = 0; mt < 4; mt++)
#pragma unroll
                for (int nt = 0; nt < 4; nt++)
                    mma_tf32(acc[mt][nt], af[mt], bf[nt]);
        }
        __syncthreads();
    }

#pragma unroll
    for (int mt = 0; mt < 4; mt++) {
        const int m = m0 + wm * 64 + mt * 16 + l4;
#pragma unroll
        for (int nt = 0; nt < 4; nt++) {
            const int n = n0 + wn * 32 + nt * 8 + lm * 2;
            float4 cc = acc[mt][nt];
            float2 bv = *(const float2*)(bias + n);
            cc.x += bv.x; cc.y += bv.y;
            cc.z += bv.x; cc.w += bv.y;
            if (resid) {
                float2 r0 = *(const float2*)(resid + (size_t)m * N + n);
                float2 r1 = *(const float2*)(resid + (size_t)(m + 8) * N + n);
                cc.x += r0.x; cc.y += r0.y;
                cc.z += r1.x; cc.w += r1.y;
            }
            if (RELU) {
                cc.x = fmaxf(cc.x, 0.f); cc.y = fmaxf(cc.y, 0.f);
                cc.z = fmaxf(cc.z, 0.f); cc.w = fmaxf(cc.w, 0.f);
            }
            *(float2*)(C + (size_t)m * N + n)       = make_float2(cc.x, cc.y);
            *(float2*)(C + (size_t)(m + 8) * N + n) = make_float2(cc.z, cc.w);
        }
    }
}

// ---------------- attention: one warp per (seq, head); broadcast-only smem ----------------
__global__ __launch_bounds__(32)
void attn_k(const float* __restrict__ qkv, float* __restrict__ ctx)
{
    const int sh   = blockIdx.x;
    const int seq  = sh >> 3;
    const int h    = sh & 7;
    const int lane = threadIdx.x;          // lane = query row r

    __shared__ float4 ks[W_][16], vs[W_][16];

    const float* base = qkv + (size_t)seq * W_ * D3 + h * DH;

    // stage K and V (each 32 rows x 16 float4)
#pragma unroll
    for (int i = 0; i < 16; i++) {
        int idx = i * 32 + lane;
        int row = idx >> 4, c4 = idx & 15;
        const float* src = base + (size_t)row * D3;
        ks[row][c4] = *(const float4*)(src + 512  + c4 * 4);
        vs[row][c4] = *(const float4*)(src + 1024 + c4 * 4);
    }
    // Q row in registers
    float4 q[16];
    {
        const float* qr = base + (size_t)lane * D3;
#pragma unroll
        for (int i = 0; i < 16; i++) q[i] = *(const float4*)(qr + i * 4);
    }
    __syncwarp();

    // scores: sc[c] = (q . k[c]) / 8, masked causal
    float sc[W_];
#pragma unroll
    for (int c = 0; c < W_; c++) {
        float s = 0.f;
#pragma unroll
        for (int e = 0; e < 16; e++) {
            float4 kk = ks[c][e];            // broadcast (same addr all lanes)
            s += q[e].x * kk.x + q[e].y * kk.y + q[e].z * kk.z + q[e].w * kk.w;
        }
        sc[c] = (c <= lane) ? s * 0.125f : -1e30f;
    }

    float mx = -1e30f;
#pragma unroll
    for (int c = 0; c < W_; c++) mx = fmaxf(mx, sc[c]);
    float sum = 0.f;
#pragma unroll
    for (int c = 0; c < W_; c++) { float e = expf(sc[c] - mx); sc[c] = e; sum += e; }
    float inv = 1.f / sum;

    float4 acc[16];
#pragma unroll
    for (int e = 0; e < 16; e++) acc[e] = make_float4(0.f, 0.f, 0.f, 0.f);
#pragma unroll
    for (int c = 0; c < W_; c++) {
        float p = sc[c] * inv;               // 0 for masked cols
#pragma unroll
        for (int e = 0; e < 16; e++) {
            float4 vv = vs[c][e];            // broadcast
            acc[e].x += p * vv.x; acc[e].y += p * vv.y;
            acc[e].z += p * vv.z; acc[e].w += p * vv.w;
        }
    }

    float* dst = ctx + ((size_t)seq * W_ + lane) * D_ + h * DH;
#pragma unroll
    for (int e = 0; e < 16; e++) *(float4*)(dst + e * 4) = acc[e];
}

// ---------------- LayerNorm: warp per row, 8 rows per block ----------------
__global__ __launch_bounds__(256)
void ln_k(const float* __restrict__ in, const float* __restrict__ g,
          const float* __restrict__ b, float* __restrict__ out)
{
    const int row  = blockIdx.x * 8 + (threadIdx.x >> 5);
    const int lane = threadIdx.x & 31;
    const float* x = in + (size_t)row * D_ + lane * 4;

    float4 v[4];
#pragma unroll
    for (int i = 0; i < 4; i++) v[i] = *(const float4*)(x + i * 128);

    float s = 0.f, sq = 0.f;
#pragma unroll
    for (int i = 0; i < 4; i++) {
        s  += v[i].x + v[i].y + v[i].z + v[i].w;
        sq += v[i].x * v[i].x + v[i].y * v[i].y + v[i].z * v[i].z + v[i].w * v[i].w;
    }
#pragma unroll
    for (int off = 16; off; off >>= 1) {
        s  += __shfl_xor_sync(0xffffffffu, s,  off);
        sq += __shfl_xor_sync(0xffffffffu, sq, off);
    }
    const float mean = s * (1.f / D_);
    const float rstd = rsqrtf(sq * (1.f / D_) - mean * mean + 1e-5f);

    float* o = out + (size_t)row * D_ + lane * 4;
#pragma unroll
    for (int i = 0; i < 4; i++) {
        float4 g4 = *(const float4*)(g + lane * 4 + i * 128);
        float4 b4 = *(const float4*)(b + lane * 4 + i * 128);
        float4 r;
        r.x = (v[i].x - mean) * rstd * g4.x + b4.x;
        r.y = (v[i].y - mean) * rstd * g4.y + b4.y;
        r.z = (v[i].z - mean) * rstd * g4.z + b4.z;
        r.w = (v[i].w - mean) * rstd * g4.w + b4.w;
        *(float4*)(o + i * 128) = r;
    }
}

// ---------------- head: logits (B,T,A) then values (B,T) ----------------
__global__ __launch_bounds__(256)
void head_k(const float* __restrict__ x, const float* __restrict__ Wp,
            const float* __restrict__ bp, const float* __restrict__ Wv,
            const float* __restrict__ bv, float* __restrict__ out)
{
    const int seq = blockIdx.x;
    __shared__ float tok[D_];
    const int tid = threadIdx.x;
    const float* src = x + ((size_t)seq * W_ + (W_ - 1)) * D_;
    *(float2*)&tok[tid * 2] = *(const float2*)(src + tid * 2);
    __syncthreads();
    int wid = tid >> 5, lane = tid & 31;
    if (wid < 7) {
        const float* wrow = (wid < 6) ? (Wp + wid * D_) : Wv;
        float s = 0.f;
        for (int i = lane; i < D_; i += 32) s += tok[i] * wrow[i];
#pragma unroll
        for (int off = 16; off; off >>= 1) s += __shfl_down_sync(0xffffffffu, s, off);
        if (lane == 0) {
            if (wid < 6) out[(size_t)seq * A_ + wid] = s + bp[wid];
            else         out[(size_t)NSEQ * A_ + seq] = s + bv[0];
        }
    }
}

// ---------------- launch ----------------
extern "C" void kernel_launch(void* const* d_in, const int* in_sizes, int n_in,
                              void* d_out, int out_size)
{
    const float* feats = (const float*)d_in[0];
    const float* pos   = (const float*)d_in[1];
    const float* Wqkv  = (const float*)d_in[2];
    const float* bqkv  = (const float*)d_in[3];
    const float* Wo    = (const float*)d_in[4];
    const float* bo    = (const float*)d_in[5];
    const float* ln1g  = (const float*)d_in[6];
    const float* ln1b  = (const float*)d_in[7];
    const float* W1    = (const float*)d_in[8];
    const float* b1    = (const float*)d_in[9];
    const float* W2    = (const float*)d_in[10];
    const float* b2    = (const float*)d_in[11];
    const float* ln2g  = (const float*)d_in[12];
    const float* ln2b  = (const float*)d_in[13];
    const float* Wp    = (const float*)d_in[14];
    const float* bp    = (const float*)d_in[15];
    const float* Wv    = (const float*)d_in[16];
    const float* bv    = (const float*)d_in[17];
    float* out = (float*)d_out;

    float *X, *QKV, *Hb;
    cudaGetSymbolAddress((void**)&X,   g_X);
    cudaGetSymbolAddress((void**)&QKV, g_QKV);
    cudaGetSymbolAddress((void**)&Hb,  g_H);

    static int attr_done = 0;
    if (!attr_done) {
        cudaFuncSetAttribute(tgemm_k<0>, cudaFuncAttributeMaxDynamicSharedMemorySize, TGEMM_SMEM);
        cudaFuncSetAttribute(tgemm_k<1>, cudaFuncAttributeMaxDynamicSharedMemorySize, TGEMM_SMEM);
        attr_done = 1;
    }

    buildx_k<<<(MROWS * D_ / 4) / 256, 256>>>(feats, pos);

    for (int i = 0; i < L_; i++) {
        // qkv = X @ Wqkv^T + bqkv
        tgemm_k<0><<<dim3(D3 / 128, MROWS / 128), 256, TGEMM_SMEM>>>(
            X, Wqkv + (size_t)i * D3 * D_, bqkv + i * D3, nullptr, QKV, MROWS, D3, D_);
        // attention -> ctx
        attn_k<<<NSEQ * H_, 32>>>(QKV, Hb);
        // preLN1 = X + ctx @ Wo^T + bo
        tgemm_k<0><<<dim3(D_ / 128, MROWS / 128), 256, TGEMM_SMEM>>>(
            Hb, Wo + (size_t)i * D_ * D_, bo + i * D_, X, QKV, MROWS, D_, D_);
        ln_k<<<MROWS / 8, 256>>>(QKV, ln1g + i * D_, ln1b + i * D_, X);
        // h = relu(X @ W1^T + b1)
        tgemm_k<1><<<dim3(DF / 128, MROWS / 128), 256, TGEMM_SMEM>>>(
            X, W1 + (size_t)i * DF * D_, b1 + i * DF, nullptr, Hb, MROWS, DF, D_);
        // preLN2 = X + h @ W2^T + b2
        tgemm_k<0><<<dim3(D_ / 128, MROWS / 128), 256, TGEMM_SMEM>>>(
            Hb, W2 + (size_t)i * D_ * DF, b2 + i * D_, X, QKV, MROWS, D_, DF);
        ln_k<<<MROWS / 8, 256>>>(QKV, ln2g + i * D_, ln2b + i * D_, X);
    }

    head_k<<<NSEQ, 256>>>(X, Wp, bp, Wv, bv, out);
}

// round 9
// speedup vs baseline: 3.3269x; 1.0123x over previous
#include <cuda_runtime.h>
#include <math.h>
#include <stdint.h>

// ---------------- problem constants ----------------
#define B_    8
#define T_    256
#define D_    512
#define W_    32
#define L_    4
#define A_    6
#define H_    8
#define DH    64
#define NSEQ  (B_*T_)        // 2048 sequences
#define MROWS (NSEQ*W_)      // 65536 rows
#define D3    (3*D_)         // 1536
#define DF    (4*D_)         // 2048

#define BK    32             // K chunk
#define SSTR  36             // smem row stride in floats (conflict-free fragments)
#define ABUF  (128*SSTR)     // 4608 floats per matrix tile
#define NSTAGE 3
#define TGEMM_SMEM (NSTAGE*2*ABUF*4)   // 110592 B

// converted-weight offsets (floats)
#define OFF_WQKV 0
#define OFF_WO   ((size_t)L_*D3*D_)                    // 3145728
#define OFF_W1   (OFF_WO + (size_t)L_*D_*D_)           // 4194304
#define OFF_W2   (OFF_W1 + (size_t)L_*DF*D_)           // 8388608
#define WC_TOTAL (OFF_W2 + (size_t)L_*D_*DF)           // 12582912

// ---------------- scratch (device globals; no allocations) ----------------
__device__ float g_X  [(size_t)MROWS * D_];
__device__ float g_QKV[(size_t)MROWS * D3];
__device__ float g_H  [(size_t)MROWS * DF];
__device__ float g_Wc [WC_TOTAL];                      // tf32-rounded weights

// ---------------- PTX helpers ----------------
__device__ __forceinline__ uint32_t smem_u32(const void* p) {
    uint32_t a;
    asm("{ .reg .u64 t; cvta.to.shared.u64 t, %1; cvt.u32.u64 %0, t; }" : "=r"(a) : "l"(p));
    return a;
}
__device__ __forceinline__ float f2tf32f(float f) {
    uint32_t r;
    asm("cvt.rna.tf32.f32 %0, %1;" : "=r"(r) : "f"(f));
    return __uint_as_float(r);
}
__device__ __forceinline__ void cp16(uint32_t s, const void* g) {
    asm volatile("cp.async.cg.shared.global [%0], [%1], 16;" :: "r"(s), "l"(g));
}
__device__ __forceinline__ void cp_commit() {
    asm volatile("cp.async.commit_group;" ::: "memory");
}
__device__ __forceinline__ void cp_wait1() {
    asm volatile("cp.async.wait_group 1;" ::: "memory");
}
__device__ __forceinline__ void cp_wait0() {
    asm volatile("cp.async.wait_group 0;" ::: "memory");
}
__device__ __forceinline__ void mma_tf32(float4& c, const uint32_t a[4], const uint32_t b[2]) {
    asm volatile(
        "mma.sync.aligned.m16n8k8.row.col.f32.tf32.tf32.f32 "
        "{%0,%1,%2,%3}, {%4,%5,%6,%7}, {%8,%9}, {%0,%1,%2,%3};"
        : "+f"(c.x), "+f"(c.y), "+f"(c.z), "+f"(c.w)
        : "r"(a[0]), "r"(a[1]), "r"(a[2]), "r"(a[3]), "r"(b[0]), "r"(b[1]));
}
__device__ __forceinline__ float4 round4(float4 v) {
    return make_float4(f2tf32f(v.x), f2tf32f(v.y), f2tf32f(v.z), f2tf32f(v.w));
}

// ---------------- weight tf32 pre-rounding ----------------
__global__ __launch_bounds__(256)
void cvtw_k(const float* __restrict__ src, float* __restrict__ dst, int n4)
{
    int i = blockIdx.x * 256 + threadIdx.x;
    if (i < n4) *(float4*)(dst + (size_t)i * 4) = round4(*(const float4*)(src + (size_t)i * 4));
}

// ---------------- build X = tf32(feats[window] + pos_embed) ----------------
__global__ __launch_bounds__(256)
void buildx_k(const float* __restrict__ feats, const float* __restrict__ pos)
{
    int idx = blockIdx.x * 256 + threadIdx.x;
    int d4  = idx & 127;
    int w   = (idx >> 7) & 31;
    int seq = idx >> 12;
    int t   = seq & (T_ - 1);
    int f   = t + 1 - W_ + w; if (f < 0) f = 0;
    int frame = (seq - t) + f;
    float4 a  = *(const float4*)(feats + (size_t)frame * D_ + d4 * 4);
    float4 p4 = *(const float4*)(pos   + (size_t)w     * D_ + d4 * 4);
    float4 o  = make_float4(a.x + p4.x, a.y + p4.y, a.z + p4.z, a.w + p4.w);
    *(float4*)(g_X + (size_t)idx * 4) = round4(o);
}

// ---------------- tf32 mma.sync GEMM: C = A(MxK) * Bw(NxK)^T + bias (+resid)(relu) ---------------
// Operands are PRE-ROUNDED to tf32 (bits passed straight to mma — no in-loop cvt).
// 128x128 tile, 256 threads (8 warps 2x4, warp tile 64x32), 3-stage cp.async pipeline.
template<int RELU, int ROUND>
__global__ __launch_bounds__(256)
void tgemm_k(const float* __restrict__ A, const float* __restrict__ Bw,
             const float* __restrict__ bias, const float* __restrict__ resid,
             float* __restrict__ C, int M, int N, int K)
{
    extern __shared__ float sm[];
    const uint32_t sm0 = smem_u32(sm);

    const int tid  = threadIdx.x;
    const int lane = tid & 31;
    const int wid  = tid >> 5;
    const int wm   = wid >> 2;          // 0..1
    const int wn   = wid & 3;           // 0..3
    const int l4   = lane >> 2;         // 0..7
    const int lm   = lane & 3;          // 0..3
    const int n0   = blockIdx.x * 128;
    const int m0   = blockIdx.y * 128;

    const int srow = tid >> 3;
    const int sq   = (tid & 7) * 4;

    const float* Abase = A  + (size_t)(m0 + srow) * K + sq;
    const float* Bbase = Bw + (size_t)(n0 + srow) * K + sq;
    const uint32_t sAoff = (uint32_t)(srow * SSTR + sq) * 4;

    auto stage = [&](int c) {
        int pb = c % NSTAGE;
        uint32_t sA = sm0 + (uint32_t)(pb * 2 * ABUF) * 4 + sAoff;
        uint32_t sB = sA + (uint32_t)ABUF * 4;
        const float* ga = Abase + (size_t)c * BK;
        const float* gb = Bbase + (size_t)c * BK;
#pragma unroll
        for (int i = 0; i < 4; i++) {
            cp16(sA + i * 32 * SSTR * 4, ga + (size_t)(i * 32) * K);
            cp16(sB + i * 32 * SSTR * 4, gb + (size_t)(i * 32) * K);
        }
        cp_commit();
    };

    float4 acc[4][4];
#pragma unroll
    for (int i = 0; i < 4; i++)
#pragma unroll
        for (int j = 0; j < 4; j++) acc[i][j] = make_float4(0.f, 0.f, 0.f, 0.f);

    const int nchunk = K / BK;
    stage(0);
    if (nchunk > 1) stage(1);

    for (int c = 0; c < nchunk; c++) {
        if (c + 1 < nchunk) cp_wait1();
        else                cp_wait0();
        __syncthreads();
        if (c + 2 < nchunk) stage(c + 2);

        const float* sA = sm + (c % NSTAGE) * 2 * ABUF;
        const float* sB = sA + ABUF;
        const float* aB = sA + (wm * 64 + l4) * SSTR + lm;
        const float* bB = sB + (wn * 32 + l4) * SSTR + lm;

#pragma unroll
        for (int ks = 0; ks < 4; ks++) {
            const int kk = ks * 8;
            uint32_t af[4][4], bf[4][2];
#pragma unroll
            for (int mt = 0; mt < 4; mt++) {
                const float* p = aB + mt * 16 * SSTR + kk;
                af[mt][0] = __float_as_uint(p[0]);
                af[mt][1] = __float_as_uint(p[8 * SSTR]);
                af[mt][2] = __float_as_uint(p[4]);
                af[mt][3] = __float_as_uint(p[8 * SSTR + 4]);
            }
#pragma unroll
            for (int nt = 0; nt < 4; nt++) {
                const float* p = bB + nt * 8 * SSTR + kk;
                bf[nt][0] = __float_as_uint(p[0]);
                bf[nt][1] = __float_as_uint(p[4]);
            }
#pragma unroll
            for (int mt = 0; mt < 4; mt++)
#pragma unroll
                for (int nt = 0; nt < 4; nt++)
                    mma_tf32(acc[mt][nt], af[mt], bf[nt]);
        }
        __syncthreads();
    }

#pragma unroll
    for (int mt = 0; mt < 4; mt++) {
        const int m = m0 + wm * 64 + mt * 16 + l4;
#pragma unroll
        for (int nt = 0; nt < 4; nt++) {
            const int n = n0 + wn * 32 + nt * 8 + lm * 2;
            float4 cc = acc[mt][nt];
            float2 bv = *(const float2*)(bias + n);
            cc.x += bv.x; cc.y += bv.y;
            cc.z += bv.x; cc.w += bv.y;
            if (resid) {
                float2 r0 = *(const float2*)(resid + (size_t)m * N + n);
                float2 r1 = *(const float2*)(resid + (size_t)(m + 8) * N + n);
                cc.x += r0.x; cc.y += r0.y;
                cc.z += r1.x; cc.w += r1.y;
            }
            if (RELU) {
                cc.x = fmaxf(cc.x, 0.f); cc.y = fmaxf(cc.y, 0.f);
                cc.z = fmaxf(cc.z, 0.f); cc.w = fmaxf(cc.w, 0.f);
            }
            if (ROUND) {
                cc.x = f2tf32f(cc.x); cc.y = f2tf32f(cc.y);
                cc.z = f2tf32f(cc.z); cc.w = f2tf32f(cc.w);
            }
            *(float2*)(C + (size_t)m * N + n)       = make_float2(cc.x, cc.y);
            *(float2*)(C + (size_t)(m + 8) * N + n) = make_float2(cc.z, cc.w);
        }
    }
}

// ---------------- attention: one warp per (seq, head); broadcast-only smem ----------------
__global__ __launch_bounds__(32)
void attn_k(const float* __restrict__ qkv, float* __restrict__ ctx)
{
    const int sh   = blockIdx.x;
    const int seq  = sh >> 3;
    const int h    = sh & 7;
    const int lane = threadIdx.x;

    __shared__ float4 ks[W_][16], vs[W_][16];

    const float* base = qkv + (size_t)seq * W_ * D3 + h * DH;

#pragma unroll
    for (int i = 0; i < 16; i++) {
        int idx = i * 32 + lane;
        int row = idx >> 4, c4 = idx & 15;
        const float* src = base + (size_t)row * D3;
        ks[row][c4] = *(const float4*)(src + 512  + c4 * 4);
        vs[row][c4] = *(const float4*)(src + 1024 + c4 * 4);
    }
    float4 q[16];
    {
        const float* qr = base + (size_t)lane * D3;
#pragma unroll
        for (int i = 0; i < 16; i++) q[i] = *(const float4*)(qr + i * 4);
    }
    __syncwarp();

    float sc[W_];
#pragma unroll
    for (int c = 0; c < W_; c++) {
        float s = 0.f;
#pragma unroll
        for (int e = 0; e < 16; e++) {
            float4 kk = ks[c][e];
            s += q[e].x * kk.x + q[e].y * kk.y + q[e].z * kk.z + q[e].w * kk.w;
        }
        sc[c] = (c <= lane) ? s * 0.125f : -1e30f;
    }

    float mx = -1e30f;
#pragma unroll
    for (int c = 0; c < W_; c++) mx = fmaxf(mx, sc[c]);
    float sum = 0.f;
#pragma unroll
    for (int c = 0; c < W_; c++) { float e = expf(sc[c] - mx); sc[c] = e; sum += e; }
    float inv = 1.f / sum;

    float4 acc[16];
#pragma unroll
    for (int e = 0; e < 16; e++) acc[e] = make_float4(0.f, 0.f, 0.f, 0.f);
#pragma unroll
    for (int c = 0; c < W_; c++) {
        float p = sc[c] * inv;
#pragma unroll
        for (int e = 0; e < 16; e++) {
            float4 vv = vs[c][e];
            acc[e].x += p * vv.x; acc[e].y += p * vv.y;
            acc[e].z += p * vv.z; acc[e].w += p * vv.w;
        }
    }

    float* dst = ctx + ((size_t)seq * W_ + lane) * D_ + h * DH;
#pragma unroll
    for (int e = 0; e < 16; e++) *(float4*)(dst + e * 4) = round4(acc[e]);
}

// ---------------- LayerNorm: warp per row, 8 rows per block; tf32-rounded output ----------------
__global__ __launch_bounds__(256)
void ln_k(const float* __restrict__ in, const float* __restrict__ g,
          const float* __restrict__ b, float* __restrict__ out)
{
    const int row  = blockIdx.x * 8 + (threadIdx.x >> 5);
    const int lane = threadIdx.x & 31;
    const float* x = in + (size_t)row * D_ + lane * 4;

    float4 v[4];
#pragma unroll
    for (int i = 0; i < 4; i++) v[i] = *(const float4*)(x + i * 128);

    float s = 0.f, sq = 0.f;
#pragma unroll
    for (int i = 0; i < 4; i++) {
        s  += v[i].x + v[i].y + v[i].z + v[i].w;
        sq += v[i].x * v[i].x + v[i].y * v[i].y + v[i].z * v[i].z + v[i].w * v[i].w;
    }
#pragma unroll
    for (int off = 16; off; off >>= 1) {
        s  += __shfl_xor_sync(0xffffffffu, s,  off);
        sq += __shfl_xor_sync(0xffffffffu, sq, off);
    }
    const float mean = s * (1.f / D_);
    const float rstd = rsqrtf(sq * (1.f / D_) - mean * mean + 1e-5f);

    float* o = out + (size_t)row * D_ + lane * 4;
#pragma unroll
    for (int i = 0; i < 4; i++) {
        float4 g4 = *(const float4*)(g + lane * 4 + i * 128);
        float4 b4 = *(const float4*)(b + lane * 4 + i * 128);
        float4 r;
        r.x = (v[i].x - mean) * rstd * g4.x + b4.x;
        r.y = (v[i].y - mean) * rstd * g4.y + b4.y;
        r.z = (v[i].z - mean) * rstd * g4.z + b4.z;
        r.w = (v[i].w - mean) * rstd * g4.w + b4.w;
        *(float4*)(o + i * 128) = round4(r);
    }
}

// ---------------- head: logits (B,T,A) then values (B,T) ----------------
__global__ __launch_bounds__(256)
void head_k(const float* __restrict__ x, const float* __restrict__ Wp,
            const float* __restrict__ bp, const float* __restrict__ Wv,
            const float* __restrict__ bv, float* __restrict__ out)
{
    const int seq = blockIdx.x;
    __shared__ float tok[D_];
    const int tid = threadIdx.x;
    const float* src = x + ((size_t)seq * W_ + (W_ - 1)) * D_;
    *(float2*)&tok[tid * 2] = *(const float2*)(src + tid * 2);
    __syncthreads();
    int wid = tid >> 5, lane = tid & 31;
    if (wid < 7) {
        const float* wrow = (wid < 6) ? (Wp + wid * D_) : Wv;
        float s = 0.f;
        for (int i = lane; i < D_; i += 32) s += tok[i] * wrow[i];
#pragma unroll
        for (int off = 16; off; off >>= 1) s += __shfl_down_sync(0xffffffffu, s, off);
        if (lane == 0) {
            if (wid < 6) out[(size_t)seq * A_ + wid] = s + bp[wid];
            else         out[(size_t)NSEQ * A_ + seq] = s + bv[0];
        }
    }
}

// ---------------- launch ----------------
extern "C" void kernel_launch(void* const* d_in, const int* in_sizes, int n_in,
                              void* d_out, int out_size)
{
    const float* feats = (const float*)d_in[0];
    const float* pos   = (const float*)d_in[1];
    const float* Wqkv  = (const float*)d_in[2];
    const float* bqkv  = (const float*)d_in[3];
    const float* Wo    = (const float*)d_in[4];
    const float* bo    = (const float*)d_in[5];
    const float* ln1g  = (const float*)d_in[6];
    const float* ln1b  = (const float*)d_in[7];
    const float* W1    = (const float*)d_in[8];
    const float* b1    = (const float*)d_in[9];
    const float* W2    = (const float*)d_in[10];
    const float* b2    = (const float*)d_in[11];
    const float* ln2g  = (const float*)d_in[12];
    const float* ln2b  = (const float*)d_in[13];
    const float* Wp    = (const float*)d_in[14];
    const float* bp    = (const float*)d_in[15];
    const float* Wv    = (const float*)d_in[16];
    const float* bv    = (const float*)d_in[17];
    float* out = (float*)d_out;

    float *X, *QKV, *Hb, *Wc;
    cudaGetSymbolAddress((void**)&X,   g_X);
    cudaGetSymbolAddress((void**)&QKV, g_QKV);
    cudaGetSymbolAddress((void**)&Hb,  g_H);
    cudaGetSymbolAddress((void**)&Wc,  g_Wc);

    static int attr_done = 0;
    if (!attr_done) {
        cudaFuncSetAttribute(tgemm_k<0,0>, cudaFuncAttributeMaxDynamicSharedMemorySize, TGEMM_SMEM);
        cudaFuncSetAttribute(tgemm_k<1,1>, cudaFuncAttributeMaxDynamicSharedMemorySize, TGEMM_SMEM);
        attr_done = 1;
    }

    // tf32 pre-rounded weights
    {
        int n;
        n = (int)(OFF_WO  - OFF_WQKV) / 4;
        cvtw_k<<<(n + 255) / 256, 256>>>(Wqkv, Wc + OFF_WQKV, n);
        n = (int)(OFF_W1  - OFF_WO) / 4;
        cvtw_k<<<(n + 255) / 256, 256>>>(Wo,   Wc + OFF_WO,   n);
        n = (int)(OFF_W2  - OFF_W1) / 4;
        cvtw_k<<<(n + 255) / 256, 256>>>(W1,   Wc + OFF_W1,   n);
        n = (int)(WC_TOTAL - OFF_W2) / 4;
        cvtw_k<<<(n + 255) / 256, 256>>>(W2,   Wc + OFF_W2,   n);
    }

    buildx_k<<<(MROWS * D_ / 4) / 256, 256>>>(feats, pos);

    for (int i = 0; i < L_; i++) {
        // qkv = X @ Wqkv^T + bqkv
        tgemm_k<0,0><<<dim3(D3 / 128, MROWS / 128), 256, TGEMM_SMEM>>>(
            X, Wc + OFF_WQKV + (size_t)i * D3 * D_, bqkv + i * D3, nullptr, QKV, MROWS, D3, D_);
        // attention -> ctx (tf32-rounded)
        attn_k<<<NSEQ * H_, 32>>>(QKV, Hb);
        // preLN1 = X + ctx @ Wo^T + bo
        tgemm_k<0,0><<<dim3(D_ / 128, MROWS / 128), 256, TGEMM_SMEM>>>(
            Hb, Wc + OFF_WO + (size_t)i * D_ * D_, bo + i * D_, X, QKV, MROWS, D_, D_);
        ln_k<<<MROWS / 8, 256>>>(QKV, ln1g + i * D_, ln1b + i * D_, X);
        // h = tf32(relu(X @ W1^T + b1))
        tgemm_k<1,1><<<dim3(DF / 128, MROWS / 128), 256, TGEMM_SMEM>>>(
            X, Wc + OFF_W1 + (size_t)i * DF * D_, b1 + i * DF, nullptr, Hb, MROWS, DF, D_);
        // preLN2 = X + h @ W2^T + b2
        tgemm_k<0,0><<<dim3(D_ / 128, MROWS / 128), 256, TGEMM_SMEM>>>(
            Hb, Wc + OFF_W2 + (size_t)i * D_ * DF, b2 + i * D_, X, QKV, MROWS, D_, DF);
        ln_k<<<MROWS / 8, 256>>>(QKV, ln2g + i * D_, ln2b + i * D_, X);
    }

    head_k<<<NSEQ, 256>>>(X, Wp, bp, Wv, bv, out);
}

// round 11
// speedup vs baseline: 5.4690x; 1.6439x over previous
#include <cuda_runtime.h>
#include <cuda_fp16.h>
#include <math.h>
#include <stdint.h>

// ---------------- problem constants ----------------
#define B_    8
#define T_    256
#define D_    512
#define W_    32
#define L_    4
#define A_    6
#define H_    8
#define DH    64
#define NSEQ  (B_*T_)        // 2048
#define MROWS (NSEQ*W_)      // 65536
#define D3    (3*D_)         // 1536
#define DF    (4*D_)         // 2048

#define BKH   32             // K halves per chunk (64B per row)
#define RS    40             // smem row stride in halves (80B, ldmatrix conflict-free)
#define CHB   (128*RS*2)     // 10240 B per matrix tile
#define STG   (2*CHB)        // 20480 B per stage (A+B)
#define NSTAGE 4
#define HGEMM_SMEM (NSTAGE*STG)   // 81920 B

// converted-weight offsets (halves)
#define OFF_WQKV 0
#define OFF_WO   ((size_t)L_*D3*D_)
#define OFF_W1   (OFF_WO + (size_t)L_*D_*D_)
#define OFF_W2   (OFF_W1 + (size_t)L_*DF*D_)
#define WC_TOTAL (OFF_W2 + (size_t)L_*D_*DF)

// ---------------- scratch (device globals; no allocations) ----------------
__device__ __align__(16) __half g_X  [(size_t)MROWS * D_];   // fp16 activations (GEMM A / resid)
__device__ __align__(16) float  g_QKV[(size_t)MROWS * D3];   // fp32: qkv, then preLN temp
__device__ __align__(16) __half g_H  [(size_t)MROWS * DF];   // fp16: ctx / ff hidden
__device__ __align__(16) __half g_Wc [WC_TOTAL];             // fp16 weights

// ---------------- PTX helpers ----------------
__device__ __forceinline__ uint32_t smem_u32(const void* p) {
    uint32_t a;
    asm("{ .reg .u64 t; cvta.to.shared.u64 t, %1; cvt.u32.u64 %0, t; }" : "=r"(a) : "l"(p));
    return a;
}
__device__ __forceinline__ void cp16(uint32_t s, const void* g) {
    asm volatile("cp.async.cg.shared.global [%0], [%1], 16;" :: "r"(s), "l"(g));
}
__device__ __forceinline__ void cp_commit() {
    asm volatile("cp.async.commit_group;" ::: "memory");
}
__device__ __forceinline__ void cp_wait2() { asm volatile("cp.async.wait_group 2;" ::: "memory"); }
__device__ __forceinline__ void cp_wait1() { asm volatile("cp.async.wait_group 1;" ::: "memory"); }
__device__ __forceinline__ void cp_wait0() { asm volatile("cp.async.wait_group 0;" ::: "memory"); }

__device__ __forceinline__ void ldm_x4(uint32_t r[4], uint32_t addr) {
    asm volatile("ldmatrix.sync.aligned.m8n8.x4.shared.b16 {%0,%1,%2,%3}, [%4];"
                 : "=r"(r[0]), "=r"(r[1]), "=r"(r[2]), "=r"(r[3]) : "r"(addr));
}
__device__ __forceinline__ void mma_f16(float4& c, const uint32_t a[4], const uint32_t b0, const uint32_t b1) {
    asm volatile(
        "mma.sync.aligned.m16n8k16.row.col.f32.f16.f16.f32 "
        "{%0,%1,%2,%3}, {%4,%5,%6,%7}, {%8,%9}, {%0,%1,%2,%3};"
        : "+f"(c.x), "+f"(c.y), "+f"(c.z), "+f"(c.w)
        : "r"(a[0]), "r"(a[1]), "r"(a[2]), "r"(a[3]), "r"(b0), "r"(b1));
}

// epilogue stores (overloaded on C dtype)
__device__ __forceinline__ void st2(float* p, float x, float y)  { *(float2*)p = make_float2(x, y); }
__device__ __forceinline__ void st2(__half* p, float x, float y) { *(__half2*)p = __floats2half2_rn(x, y); }

// ---------------- weight fp16 conversion ----------------
__global__ __launch_bounds__(256)
void cvtw_k(const float* __restrict__ src, __half* __restrict__ dst, int n8)
{
    int i = blockIdx.x * 256 + threadIdx.x;
    if (i >= n8) return;
    const float4 a = *(const float4*)(src + (size_t)i * 8);
    const float4 b = *(const float4*)(src + (size_t)i * 8 + 4);
    __half2 h[4];
    h[0] = __floats2half2_rn(a.x, a.y);
    h[1] = __floats2half2_rn(a.z, a.w);
    h[2] = __floats2half2_rn(b.x, b.y);
    h[3] = __floats2half2_rn(b.z, b.w);
    *(uint2*)(dst + (size_t)i * 8)     = *(uint2*)&h[0];
    *(uint2*)(dst + (size_t)i * 8 + 4) = *(uint2*)&h[2];
}

// ---------------- build X = fp16(feats[window] + pos_embed) ----------------
__global__ __launch_bounds__(256)
void buildx_k(const float* __restrict__ feats, const float* __restrict__ pos)
{
    int idx = blockIdx.x * 256 + threadIdx.x;     // 8 halves per thread
    int d8  = idx & 63;                           // D/8
    int w   = (idx >> 6) & 31;
    int seq = idx >> 11;
    int t   = seq & (T_ - 1);
    int f   = t + 1 - W_ + w; if (f < 0) f = 0;
    int frame = (seq - t) + f;
    const float* fa = feats + (size_t)frame * D_ + d8 * 8;
    const float* pp = pos   + (size_t)w     * D_ + d8 * 8;
    float4 a0 = *(const float4*)fa, a1 = *(const float4*)(fa + 4);
    float4 p0 = *(const float4*)pp, p1 = *(const float4*)(pp + 4);
    __half2 h[4];
    h[0] = __floats2half2_rn(a0.x + p0.x, a0.y + p0.y);
    h[1] = __floats2half2_rn(a0.z + p0.z, a0.w + p0.w);
    h[2] = __floats2half2_rn(a1.x + p1.x, a1.y + p1.y);
    h[3] = __floats2half2_rn(a1.z + p1.z, a1.w + p1.w);
    __half* dst = g_X + (size_t)idx * 8;
    *(uint2*)dst       = *(uint2*)&h[0];
    *(uint2*)(dst + 4) = *(uint2*)&h[2];
}

// ---------------- fp16 mma.sync GEMM: C = A(MxK) * Bw(NxK)^T + bias (+resid)(relu) ----------------
// 128x128 tile, 256 threads (8 warps 2x4, warp tile 64x32), 4-stage cp.async, ldmatrix fragments.
template<int RELU, typename TC>
__global__ __launch_bounds__(256, 2)
void hgemm_k(const __half* __restrict__ A, const __half* __restrict__ Bw,
             const float* __restrict__ bias, const __half* __restrict__ resid,
             TC* __restrict__ C, int M, int N, int K)
{
    extern __shared__ __half sh[];
    const uint32_t sm0 = smem_u32(sh);

    const int tid  = threadIdx.x;
    const int lane = tid & 31;
    const int wid  = tid >> 5;
    const int wm   = wid >> 2;          // 0..1
    const int wn   = wid & 3;           // 0..3
    const int l4   = lane >> 2;
    const int lm   = lane & 3;
    const int n0   = blockIdx.x * 128;
    const int m0   = blockIdx.y * 128;

    // staging: per matrix 512 x 16B units; thread covers units tid and tid+256
    const int row0 = tid >> 2;          // unit tid
    const int prt0 = tid & 3;
    const __half* Au = A  + (size_t)(m0 + row0) * K + prt0 * 8;
    const __half* Bu = Bw + (size_t)(n0 + row0) * K + prt0 * 8;
    const uint32_t du = (uint32_t)(row0 * RS + prt0 * 8) * 2;
    const __half* Au2 = Au + (size_t)64 * K;     // unit tid+256: row0+64
    const __half* Bu2 = Bu + (size_t)64 * K;
    const uint32_t du2 = du + 64 * RS * 2;

    auto stage = [&](int c) {
        uint32_t base = sm0 + (uint32_t)(c & 3) * STG;
        const size_t ko = (size_t)c * BKH;
        cp16(base + du,          Au  + ko);
        cp16(base + du2,         Au2 + ko);
        cp16(base + CHB + du,    Bu  + ko);
        cp16(base + CHB + du2,   Bu2 + ko);
        cp_commit();
    };

    // ldmatrix lane address components
    const int rA   = lane & 15;
    const int kofA = (lane >> 4) * 8;
    const int rB   = lane & 7;
    const int kofB = ((lane >> 3) & 1) * 8;
    const int whB  = (lane >> 4) * 8;           // which n8 tile within pair

    const uint32_t aoffs = (uint32_t)((wm * 64 + rA) * RS + kofA) * 2;
    const uint32_t boffs = (uint32_t)(CHB) + (uint32_t)((wn * 32 + whB + rB) * RS + kofB) * 2;

    float4 acc[4][4];
#pragma unroll
    for (int i = 0; i < 4; i++)
#pragma unroll
        for (int j = 0; j < 4; j++) acc[i][j] = make_float4(0.f, 0.f, 0.f, 0.f);

    const int nchunk = K / BKH;
    stage(0); stage(1); stage(2);

    for (int c = 0; c < nchunk; c++) {
        const int rem = nchunk - 1 - c;
        if (rem >= 2)      cp_wait2();
        else if (rem == 1) cp_wait1();
        else               cp_wait0();
        __syncthreads();
        if (c + 3 < nchunk) stage(c + 3);

        const uint32_t base = sm0 + (uint32_t)(c & 3) * STG;
#pragma unroll
        for (int ks = 0; ks < 2; ks++) {
            uint32_t af[4][4], bf[2][4];
#pragma unroll
            for (int mt = 0; mt < 4; mt++)
                ldm_x4(af[mt], base + aoffs + (uint32_t)(mt * 16 * RS + ks * 16) * 2);
#pragma unroll
            for (int ntp = 0; ntp < 2; ntp++)
                ldm_x4(bf[ntp], base + boffs + (uint32_t)(ntp * 16 * RS + ks * 16) * 2);
#pragma unroll
            for (int mt = 0; mt < 4; mt++)
#pragma unroll
                for (int nt = 0; nt < 4; nt++)
                    mma_f16(acc[mt][nt], af[mt], bf[nt >> 1][(nt & 1) * 2], bf[nt >> 1][(nt & 1) * 2 + 1]);
        }
        __syncthreads();
    }

    // epilogue: bias (+resid)(relu)
#pragma unroll
    for (int mt = 0; mt < 4; mt++) {
        const int m = m0 + wm * 64 + mt * 16 + l4;
#pragma unroll
        for (int nt = 0; nt < 4; nt++) {
            const int n = n0 + wn * 32 + nt * 8 + lm * 2;
            float4 cc = acc[mt][nt];
            float2 bv = *(const float2*)(bias + n);
            cc.x += bv.x; cc.y += bv.y;
            cc.z += bv.x; cc.w += bv.y;
            if (resid) {
                float2 r0 = __half22float2(*(const __half2*)(resid + (size_t)m * N + n));
                float2 r1 = __half22float2(*(const __half2*)(resid + (size_t)(m + 8) * N + n));
                cc.x += r0.x; cc.y += r0.y;
                cc.z += r1.x; cc.w += r1.y;
            }
            if (RELU) {
                cc.x = fmaxf(cc.x, 0.f); cc.y = fmaxf(cc.y, 0.f);
                cc.z = fmaxf(cc.z, 0.f); cc.w = fmaxf(cc.w, 0.f);
            }
            st2(C + (size_t)m * N + n,       cc.x, cc.y);
            st2(C + (size_t)(m + 8) * N + n, cc.z, cc.w);
        }
    }
}

// ---------------- attention: one warp per (seq, head); qkv fp32, ctx fp16 ----------------
__global__ __launch_bounds__(32)
void attn_k(const float* __restrict__ qkv, __half* __restrict__ ctx)
{
    const int sh   = blockIdx.x;
    const int seq  = sh >> 3;
    const int h    = sh & 7;
    const int lane = threadIdx.x;

    __shared__ float4 ks[W_][16], vs[W_][16];

    const float* base = qkv + (size_t)seq * W_ * D3 + h * DH;

#pragma unroll
    for (int i = 0; i < 16; i++) {
        int idx = i * 32 + lane;
        int row = idx >> 4, c4 = idx & 15;
        const float* src = base + (size_t)row * D3;
        ks[row][c4] = *(const float4*)(src + 512  + c4 * 4);
        vs[row][c4] = *(const float4*)(src + 1024 + c4 * 4);
    }
    float4 q[16];
    {
        const float* qr = base + (size_t)lane * D3;
#pragma unroll
        for (int i = 0; i < 16; i++) q[i] = *(const float4*)(qr + i * 4);
    }
    __syncwarp();

    float sc[W_];
#pragma unroll
    for (int c = 0; c < W_; c++) {
        float s = 0.f;
#pragma unroll
        for (int e = 0; e < 16; e++) {
            float4 kk = ks[c][e];
            s += q[e].x * kk.x + q[e].y * kk.y + q[e].z * kk.z + q[e].w * kk.w;
        }
        sc[c] = (c <= lane) ? s * 0.125f : -1e30f;
    }

    float mx = -1e30f;
#pragma unroll
    for (int c = 0; c < W_; c++) mx = fmaxf(mx, sc[c]);
    float sum = 0.f;
#pragma unroll
    for (int c = 0; c < W_; c++) { float e = expf(sc[c] - mx); sc[c] = e; sum += e; }
    float inv = 1.f / sum;

    float4 acc[16];
#pragma unroll
    for (int e = 0; e < 16; e++) acc[e] = make_float4(0.f, 0.f, 0.f, 0.f);
#pragma unroll
    for (int c = 0; c < W_; c++) {
        float p = sc[c] * inv;
#pragma unroll
        for (int e = 0; e < 16; e++) {
            float4 vv = vs[c][e];
            acc[e].x += p * vv.x; acc[e].y += p * vv.y;
            acc[e].z += p * vv.z; acc[e].w += p * vv.w;
        }
    }

    __half* dst = ctx + ((size_t)seq * W_ + lane) * D_ + h * DH;
#pragma unroll
    for (int e = 0; e < 16; e++) {
        *(__half2*)(dst + e * 4)     = __floats2half2_rn(acc[e].x, acc[e].y);
        *(__half2*)(dst + e * 4 + 2) = __floats2half2_rn(acc[e].z, acc[e].w);
    }
}

// ---------------- LayerNorm: warp per row; fp32 in -> fp16 out ----------------
__global__ __launch_bounds__(256)
void ln_k(const float* __restrict__ in, const float* __restrict__ g,
          const float* __restrict__ b, __half* __restrict__ out)
{
    const int row  = blockIdx.x * 8 + (threadIdx.x >> 5);
    const int lane = threadIdx.x & 31;
    const float* x = in + (size_t)row * D_ + lane * 4;

    float4 v[4];
#pragma unroll
    for (int i = 0; i < 4; i++) v[i] = *(const float4*)(x + i * 128);

    float s = 0.f, sq = 0.f;
#pragma unroll
    for (int i = 0; i < 4; i++) {
        s  += v[i].x + v[i].y + v[i].z + v[i].w;
        sq += v[i].x * v[i].x + v[i].y * v[i].y + v[i].z * v[i].z + v[i].w * v[i].w;
    }
#pragma unroll
    for (int off = 16; off; off >>= 1) {
        s  += __shfl_xor_sync(0xffffffffu, s,  off);
        sq += __shfl_xor_sync(0xffffffffu, sq, off);
    }
    const float mean = s * (1.f / D_);
    const float rstd = rsqrtf(sq * (1.f / D_) - mean * mean + 1e-5f);

    __half* o = out + (size_t)row * D_ + lane * 4;
#pragma unroll
    for (int i = 0; i < 4; i++) {
        float4 g4 = *(const float4*)(g + lane * 4 + i * 128);
        float4 b4 = *(const float4*)(b + lane * 4 + i * 128);
        float rx = (v[i].x - mean) * rstd * g4.x + b4.x;
        float ry = (v[i].y - mean) * rstd * g4.y + b4.y;
        float rz = (v[i].z - mean) * rstd * g4.z + b4.z;
        float rw = (v[i].w - mean) * rstd * g4.w + b4.w;
        *(__half2*)(o + i * 128)     = __floats2half2_rn(rx, ry);
        *(__half2*)(o + i * 128 + 2) = __floats2half2_rn(rz, rw);
    }
}

// ---------------- head: logits (B,T,A) then values (B,T) ----------------
__global__ __launch_bounds__(256)
void head_k(const __half* __restrict__ x, const float* __restrict__ Wp,
            const float* __restrict__ bp, const float* __restrict__ Wv,
            const float* __restrict__ bv, float* __restrict__ out)
{
    const int seq = blockIdx.x;
    __shared__ float tok[D_];
    const int tid = threadIdx.x;
    const __half* src = x + ((size_t)seq * W_ + (W_ - 1)) * D_;
    float2 f = __half22float2(*(const __half2*)(src + tid * 2));
    tok[tid * 2] = f.x; tok[tid * 2 + 1] = f.y;
    __syncthreads();
    int wid = tid >> 5, lane = tid & 31;
    if (wid < 7) {
        const float* wrow = (wid < 6) ? (Wp + wid * D_) : Wv;
        float s = 0.f;
        for (int i = lane; i < D_; i += 32) s += tok[i] * wrow[i];
#pragma unroll
        for (int off = 16; off; off >>= 1) s += __shfl_down_sync(0xffffffffu, s, off);
        if (lane == 0) {
            if (wid < 6) out[(size_t)seq * A_ + wid] = s + bp[wid];
            else         out[(size_t)NSEQ * A_ + seq] = s + bv[0];
        }
    }
}

// ---------------- launch ----------------
extern "C" void kernel_launch(void* const* d_in, const int* in_sizes, int n_in,
                              void* d_out, int out_size)
{
    const float* feats = (const float*)d_in[0];
    const float* pos   = (const float*)d_in[1];
    const float* Wqkv  = (const float*)d_in[2];
    const float* bqkv  = (const float*)d_in[3];
    const float* Wo    = (const float*)d_in[4];
    const float* bo    = (const float*)d_in[5];
    const float* ln1g  = (const float*)d_in[6];
    const float* ln1b  = (const float*)d_in[7];
    const float* W1    = (const float*)d_in[8];
    const float* b1    = (const float*)d_in[9];
    const float* W2    = (const float*)d_in[10];
    const float* b2    = (const float*)d_in[11];
    const float* ln2g  = (const float*)d_in[12];
    const float* ln2b  = (const float*)d_in[13];
    const float* Wp    = (const float*)d_in[14];
    const float* bp    = (const float*)d_in[15];
    const float* Wv    = (const float*)d_in[16];
    const float* bv    = (const float*)d_in[17];
    float* out = (float*)d_out;

    __half *X, *Hb, *Wc;
    float *QKV;
    cudaGetSymbolAddress((void**)&X,   g_X);
    cudaGetSymbolAddress((void**)&QKV, g_QKV);
    cudaGetSymbolAddress((void**)&Hb,  g_H);
    cudaGetSymbolAddress((void**)&Wc,  g_Wc);

    static int attr_done = 0;
    if (!attr_done) {
        cudaFuncSetAttribute(hgemm_k<0, float>,  cudaFuncAttributeMaxDynamicSharedMemorySize, HGEMM_SMEM);
        cudaFuncSetAttribute(hgemm_k<1, __half>, cudaFuncAttributeMaxDynamicSharedMemorySize, HGEMM_SMEM);
        attr_done = 1;
    }

    // fp16 weights
    {
        int n;
        n = (int)((OFF_WO  - OFF_WQKV) / 8);
        cvtw_k<<<(n + 255) / 256, 256>>>(Wqkv, Wc + OFF_WQKV, n);
        n = (int)((OFF_W1  - OFF_WO) / 8);
        cvtw_k<<<(n + 255) / 256, 256>>>(Wo,   Wc + OFF_WO,   n);
        n = (int)((OFF_W2  - OFF_W1) / 8);
        cvtw_k<<<(n + 255) / 256, 256>>>(W1,   Wc + OFF_W1,   n);
        n = (int)((WC_TOTAL - OFF_W2) / 8);
        cvtw_k<<<(n + 255) / 256, 256>>>(W2,   Wc + OFF_W2,   n);
    }

    buildx_k<<<(MROWS * D_ / 8) / 256, 256>>>(feats, pos);

    for (int i = 0; i < L_; i++) {
        // qkv(fp32) = X @ Wqkv^T + bqkv
        hgemm_k<0, float><<<dim3(D3 / 128, MROWS / 128), 256, HGEMM_SMEM>>>(
            X, Wc + OFF_WQKV + (size_t)i * D3 * D_, bqkv + i * D3, nullptr, QKV, MROWS, D3, D_);
        // attention -> ctx (fp16)
        attn_k<<<NSEQ * H_, 32>>>(QKV, Hb);
        // preLN1(fp32) = X + ctx @ Wo^T + bo
        hgemm_k<0, float><<<dim3(D_ / 128, MROWS / 128), 256, HGEMM_SMEM>>>(
            Hb, Wc + OFF_WO + (size_t)i * D_ * D_, bo + i * D_, X, QKV, MROWS, D_, D_);
        ln_k<<<MROWS / 8, 256>>>(QKV, ln1g + i * D_, ln1b + i * D_, X);
        // h(fp16) = relu(X @ W1^T + b1)
        hgemm_k<1, __half><<<dim3(DF / 128, MROWS / 128), 256, HGEMM_SMEM>>>(
            X, Wc + OFF_W1 + (size_t)i * DF * D_, b1 + i * DF, nullptr, Hb, MROWS, DF, D_);
        // preLN2(fp32) = X + h @ W2^T + b2
        hgemm_k<0, float><<<dim3(D_ / 128, MROWS / 128), 256, HGEMM_SMEM>>>(
            Hb, Wc + OFF_W2 + (size_t)i * D_ * DF, b2 + i * D_, X, QKV, MROWS, D_, DF);
        ln_k<<<MROWS / 8, 256>>>(QKV, ln2g + i * D_, ln2b + i * D_, X);
    }

    head_k<<<NSEQ, 256>>>(X, Wp, bp, Wv, bv, out);
}